// round 2
// baseline (speedup 1.0000x reference)
#include <cuda_runtime.h>
#include <cuda_bf16.h>
#include <math.h>

// ---------------------------------------------------------------------------
// Transformer encoder block, fp32.
// B=4, S=2048, D=1024, H=16, d_k=64, FFN=4096
// ---------------------------------------------------------------------------

#define D_MODEL 1024
#define N_HEADS 16
#define D_K     64
#define D_FF    4096
#define SEQ     2048
#define BATCH   4
#define M_ROWS  (BATCH * SEQ)          // 8192

// Scratch (device globals; allocation in kernel_launch is forbidden)
__device__ float g_Q  [M_ROWS * D_MODEL];
__device__ float g_K  [M_ROWS * D_MODEL];
__device__ float g_V  [M_ROWS * D_MODEL];
__device__ float g_ctx[M_ROWS * D_MODEL];
__device__ float g_prj[M_ROWS * D_MODEL];
__device__ float g_h  [M_ROWS * D_MODEL];
__device__ float g_mid[(size_t)M_ROWS * D_FF];
__device__ float g_f  [M_ROWS * D_MODEL];

// ---------------------------------------------------------------------------
// SGEMM: C[M,N] = A[M,K] @ B[K,N] + bias (+ optional ReLU)
// BM=BN=128, BK=16, 256 threads, 8x8 per thread.
// Requires M%128==0, N%128==0, K%16==0 (true for all calls here).
// ---------------------------------------------------------------------------
__global__ __launch_bounds__(256) void sgemm_bias_kernel(
    const float* __restrict__ A, const float* __restrict__ B,
    const float* __restrict__ bias, float* __restrict__ C,
    int M, int N, int K, int relu)
{
    __shared__ float As[16][128];
    __shared__ float Bs[16][128];

    const int tid = threadIdx.x;
    const int bm  = blockIdx.y;
    const int bn  = blockIdx.x;
    const int tr  = tid >> 4;          // 0..15
    const int tc  = tid & 15;          // 0..15

    const float* Ab = A + (size_t)bm * 128 * K;
    const float* Bb = B + (size_t)bn * 128;

    const int arow = tid >> 2;         // 0..63
    const int acol = (tid & 3) * 4;    // 0,4,8,12
    const int brow = tid >> 5;         // 0..7
    const int bcol = (tid & 31) * 4;   // 0..124

    float acc[8][8];
    #pragma unroll
    for (int i = 0; i < 8; i++)
        #pragma unroll
        for (int j = 0; j < 8; j++) acc[i][j] = 0.0f;

    for (int kk = 0; kk < K; kk += 16) {
        float4 a0 = *(const float4*)(Ab + (size_t)arow        * K + kk + acol);
        float4 a1 = *(const float4*)(Ab + (size_t)(arow + 64) * K + kk + acol);
        As[acol + 0][arow]      = a0.x;
        As[acol + 1][arow]      = a0.y;
        As[acol + 2][arow]      = a0.z;
        As[acol + 3][arow]      = a0.w;
        As[acol + 0][arow + 64] = a1.x;
        As[acol + 1][arow + 64] = a1.y;
        As[acol + 2][arow + 64] = a1.z;
        As[acol + 3][arow + 64] = a1.w;

        float4 b0 = *(const float4*)(Bb + (size_t)(kk + brow)     * N + bcol);
        float4 b1 = *(const float4*)(Bb + (size_t)(kk + brow + 8) * N + bcol);
        *(float4*)&Bs[brow][bcol]     = b0;
        *(float4*)&Bs[brow + 8][bcol] = b1;

        __syncthreads();

        #pragma unroll
        for (int k = 0; k < 16; k++) {
            float rm[8], rn[8];
            #pragma unroll
            for (int i = 0; i < 8; i++) rm[i] = As[k][tr * 8 + i];
            #pragma unroll
            for (int j = 0; j < 8; j++) rn[j] = Bs[k][tc * 8 + j];
            #pragma unroll
            for (int i = 0; i < 8; i++)
                #pragma unroll
                for (int j = 0; j < 8; j++)
                    acc[i][j] += rm[i] * rn[j];
        }
        __syncthreads();
    }

    const int colbase = bn * 128 + tc * 8;
    float bvals[8];
    #pragma unroll
    for (int j = 0; j < 8; j++) bvals[j] = bias[colbase + j];

    #pragma unroll
    for (int i = 0; i < 8; i++) {
        int row = bm * 128 + tr * 8 + i;
        float* Cr = C + (size_t)row * N + colbase;
        float4 r0, r1;
        r0.x = acc[i][0] + bvals[0]; r0.y = acc[i][1] + bvals[1];
        r0.z = acc[i][2] + bvals[2]; r0.w = acc[i][3] + bvals[3];
        r1.x = acc[i][4] + bvals[4]; r1.y = acc[i][5] + bvals[5];
        r1.z = acc[i][6] + bvals[6]; r1.w = acc[i][7] + bvals[7];
        if (relu) {
            r0.x = fmaxf(r0.x, 0.f); r0.y = fmaxf(r0.y, 0.f);
            r0.z = fmaxf(r0.z, 0.f); r0.w = fmaxf(r0.w, 0.f);
            r1.x = fmaxf(r1.x, 0.f); r1.y = fmaxf(r1.y, 0.f);
            r1.z = fmaxf(r1.z, 0.f); r1.w = fmaxf(r1.w, 0.f);
        }
        *(float4*)(Cr)     = r0;
        *(float4*)(Cr + 4) = r1;
    }
}

// ---------------------------------------------------------------------------
// Flash-attention style kernel (fp32).
// grid: (SEQ/64, N_HEADS, BATCH), block 256.
// Q tile 64x64 resident; stream K/V in 32-row tiles with online softmax.
// Layouts: Q/K/V/O are [8192, 1024]; head h occupies cols [h*64, h*64+64).
// ---------------------------------------------------------------------------
__global__ __launch_bounds__(256) void attn_kernel(
    const float* __restrict__ Q, const float* __restrict__ K,
    const float* __restrict__ V, float* __restrict__ O)
{
    const int b  = blockIdx.z;
    const int h  = blockIdx.y;
    const int qt = blockIdx.x;
    const int tid = threadIdx.x;

    __shared__ float Qs[64][68];     // padded: stride 68 (float4-aligned)
    __shared__ float KVs[32][68];    // K tile, then reused for V tile
    __shared__ float Ps[64][33];     // softmax probabilities (padded)
    __shared__ float m_s[64], l_s[64], fac_s[64], tmax_s[64], tsum_s[64];

    const size_t qrow0 = (size_t)b * SEQ + (size_t)qt * 64;
    const float* Qb = Q + qrow0 * D_MODEL + h * D_K;
    const float* Kb = K + (size_t)b * SEQ * D_MODEL + h * D_K;
    const float* Vb = V + (size_t)b * SEQ * D_MODEL + h * D_K;

    // load Q tile (64 x 64)
    for (int t = tid; t < 64 * 16; t += 256) {
        int r = t >> 4, c4 = (t & 15) * 4;
        *(float4*)&Qs[r][c4] = *(const float4*)(Qb + (size_t)r * D_MODEL + c4);
    }
    if (tid < 64) { m_s[tid] = -1e30f; l_s[tid] = 0.0f; }

    // S-phase mapping: 2 rows x 4 cols per thread
    const int is0 = (tid >> 3) * 2;      // 0..62
    const int js0 = (tid & 7) * 4;       // 0..28
    // O-phase mapping: 4 rows x 4 d-cols per thread
    const int io0 = (tid >> 4) * 4;      // 0..60
    const int d0  = (tid & 15) * 4;      // 0..60

    float o[4][4];
    #pragma unroll
    for (int r = 0; r < 4; r++)
        #pragma unroll
        for (int c = 0; c < 4; c++) o[r][c] = 0.0f;

    __syncthreads();

    for (int kt = 0; kt < SEQ / 32; kt++) {
        // load K tile (32 x 64)
        for (int t = tid; t < 32 * 16; t += 256) {
            int r = t >> 4, c4 = (t & 15) * 4;
            *(float4*)&KVs[r][c4] =
                *(const float4*)(Kb + (size_t)(kt * 32 + r) * D_MODEL + c4);
        }
        __syncthreads();

        // S = scale * Q K^T  (2x4 per thread)
        float s[2][4];
        #pragma unroll
        for (int r = 0; r < 2; r++)
            #pragma unroll
            for (int c = 0; c < 4; c++) s[r][c] = 0.0f;

        #pragma unroll
        for (int d = 0; d < 64; d += 4) {
            float4 q0 = *(float4*)&Qs[is0][d];
            float4 q1 = *(float4*)&Qs[is0 + 1][d];
            #pragma unroll
            for (int c = 0; c < 4; c++) {
                float4 kv = *(float4*)&KVs[js0 + c][d];
                s[0][c] += q0.x * kv.x + q0.y * kv.y + q0.z * kv.z + q0.w * kv.w;
                s[1][c] += q1.x * kv.x + q1.y * kv.y + q1.z * kv.z + q1.w * kv.w;
            }
        }
        #pragma unroll
        for (int r = 0; r < 2; r++)
            #pragma unroll
            for (int c = 0; c < 4; c++) s[r][c] *= 0.125f;   // 1/sqrt(64)

        // row max across the 8 threads that share each row
        #pragma unroll
        for (int r = 0; r < 2; r++) {
            float mx = fmaxf(fmaxf(s[r][0], s[r][1]), fmaxf(s[r][2], s[r][3]));
            mx = fmaxf(mx, __shfl_xor_sync(0xffffffffu, mx, 1));
            mx = fmaxf(mx, __shfl_xor_sync(0xffffffffu, mx, 2));
            mx = fmaxf(mx, __shfl_xor_sync(0xffffffffu, mx, 4));
            if ((tid & 7) == 0) tmax_s[is0 + r] = mx;
        }
        __syncthreads();

        if (tid < 64) {
            float mo = m_s[tid];
            float mn = fmaxf(mo, tmax_s[tid]);
            fac_s[tid] = __expf(mo - mn);
            m_s[tid] = mn;
        }
        __syncthreads();

        // P = exp(S - m_new), row sums
        #pragma unroll
        for (int r = 0; r < 2; r++) {
            float mn = m_s[is0 + r];
            float sum = 0.0f;
            #pragma unroll
            for (int c = 0; c < 4; c++) {
                float p = __expf(s[r][c] - mn);
                Ps[is0 + r][js0 + c] = p;
                sum += p;
            }
            sum += __shfl_xor_sync(0xffffffffu, sum, 1);
            sum += __shfl_xor_sync(0xffffffffu, sum, 2);
            sum += __shfl_xor_sync(0xffffffffu, sum, 4);
            if ((tid & 7) == 0) tsum_s[is0 + r] = sum;
        }
        __syncthreads();

        if (tid < 64) l_s[tid] = l_s[tid] * fac_s[tid] + tsum_s[tid];

        // load V tile (overwrites K tile; all reads of K are done)
        for (int t = tid; t < 32 * 16; t += 256) {
            int r = t >> 4, c4 = (t & 15) * 4;
            *(float4*)&KVs[r][c4] =
                *(const float4*)(Vb + (size_t)(kt * 32 + r) * D_MODEL + c4);
        }
        __syncthreads();

        // O = O * fac + P @ V
        float f0 = fac_s[io0 + 0], f1 = fac_s[io0 + 1];
        float f2 = fac_s[io0 + 2], f3 = fac_s[io0 + 3];
        #pragma unroll
        for (int c = 0; c < 4; c++) {
            o[0][c] *= f0; o[1][c] *= f1; o[2][c] *= f2; o[3][c] *= f3;
        }
        #pragma unroll
        for (int j = 0; j < 32; j++) {
            float4 v4 = *(float4*)&KVs[j][d0];
            float p0 = Ps[io0 + 0][j];
            float p1 = Ps[io0 + 1][j];
            float p2 = Ps[io0 + 2][j];
            float p3 = Ps[io0 + 3][j];
            o[0][0] += p0 * v4.x; o[0][1] += p0 * v4.y; o[0][2] += p0 * v4.z; o[0][3] += p0 * v4.w;
            o[1][0] += p1 * v4.x; o[1][1] += p1 * v4.y; o[1][2] += p1 * v4.z; o[1][3] += p1 * v4.w;
            o[2][0] += p2 * v4.x; o[2][1] += p2 * v4.y; o[2][2] += p2 * v4.z; o[2][3] += p2 * v4.w;
            o[3][0] += p3 * v4.x; o[3][1] += p3 * v4.y; o[3][2] += p3 * v4.z; o[3][3] += p3 * v4.w;
        }
        __syncthreads();   // protect KVs/Ps before next tile overwrites
    }

    // final normalize + store
    #pragma unroll
    for (int r = 0; r < 4; r++) {
        float inv = 1.0f / l_s[io0 + r];
        float4 res;
        res.x = o[r][0] * inv; res.y = o[r][1] * inv;
        res.z = o[r][2] * inv; res.w = o[r][3] * inv;
        *(float4*)(O + (qrow0 + io0 + r) * D_MODEL + h * D_K + d0) = res;
    }
}

// ---------------------------------------------------------------------------
// Fused residual-add + LayerNorm: out = LN(a + b) * g + beta
// One block (256 threads) per row of 1024; one float4 per thread.
// ---------------------------------------------------------------------------
__global__ __launch_bounds__(256) void add_ln_kernel(
    const float* __restrict__ a, const float* __restrict__ b,
    const float* __restrict__ g, const float* __restrict__ beta,
    float* __restrict__ out)
{
    const int row = blockIdx.x;
    const int tid = threadIdx.x;

    const float4 av = *(const float4*)(a + (size_t)row * D_MODEL + tid * 4);
    const float4 bv = *(const float4*)(b + (size_t)row * D_MODEL + tid * 4);
    float4 v;
    v.x = av.x + bv.x; v.y = av.y + bv.y; v.z = av.z + bv.z; v.w = av.w + bv.w;

    float s  = v.x + v.y + v.z + v.w;
    float sq = v.x * v.x + v.y * v.y + v.z * v.z + v.w * v.w;

    #pragma unroll
    for (int off = 16; off; off >>= 1) {
        s  += __shfl_xor_sync(0xffffffffu, s,  off);
        sq += __shfl_xor_sync(0xffffffffu, sq, off);
    }
    __shared__ float red_s[8], red_q[8];
    if ((tid & 31) == 0) { red_s[tid >> 5] = s; red_q[tid >> 5] = sq; }
    __syncthreads();
    __shared__ float smean, srstd;
    if (tid == 0) {
        float ts = 0.f, tq = 0.f;
        #pragma unroll
        for (int i = 0; i < 8; i++) { ts += red_s[i]; tq += red_q[i]; }
        float mean = ts * (1.0f / D_MODEL);
        float var  = tq * (1.0f / D_MODEL) - mean * mean;
        smean = mean;
        srstd = rsqrtf(var + 1e-5f);
    }
    __syncthreads();
    const float mean = smean, rstd = srstd;

    const float4 gv = *(const float4*)(g    + tid * 4);
    const float4 tv = *(const float4*)(beta + tid * 4);
    float4 o;
    o.x = (v.x - mean) * rstd * gv.x + tv.x;
    o.y = (v.y - mean) * rstd * gv.y + tv.y;
    o.z = (v.z - mean) * rstd * gv.z + tv.z;
    o.w = (v.w - mean) * rstd * gv.w + tv.w;
    *(float4*)(out + (size_t)row * D_MODEL + tid * 4) = o;
}

// ---------------------------------------------------------------------------
// Launch
// ---------------------------------------------------------------------------
extern "C" void kernel_launch(void* const* d_in, const int* in_sizes, int n_in,
                              void* d_out, int out_size)
{
    const float* x     = (const float*)d_in[0];
    const float* Wq    = (const float*)d_in[1];
    const float* bq    = (const float*)d_in[2];
    const float* Wk    = (const float*)d_in[3];
    const float* bk    = (const float*)d_in[4];
    const float* Wv    = (const float*)d_in[5];
    const float* bv    = (const float*)d_in[6];
    const float* Wo    = (const float*)d_in[7];
    const float* bo    = (const float*)d_in[8];
    const float* ln1_g = (const float*)d_in[9];
    const float* ln1_b = (const float*)d_in[10];
    const float* W1    = (const float*)d_in[11];
    const float* b1    = (const float*)d_in[12];
    const float* W2    = (const float*)d_in[13];
    const float* b2    = (const float*)d_in[14];
    const float* ln2_g = (const float*)d_in[15];
    const float* ln2_b = (const float*)d_in[16];
    float* out = (float*)d_out;

    float *pQ, *pK, *pV, *pCtx, *pPrj, *pH, *pMid, *pF;
    cudaGetSymbolAddress((void**)&pQ,   g_Q);
    cudaGetSymbolAddress((void**)&pK,   g_K);
    cudaGetSymbolAddress((void**)&pV,   g_V);
    cudaGetSymbolAddress((void**)&pCtx, g_ctx);
    cudaGetSymbolAddress((void**)&pPrj, g_prj);
    cudaGetSymbolAddress((void**)&pH,   g_h);
    cudaGetSymbolAddress((void**)&pMid, g_mid);
    cudaGetSymbolAddress((void**)&pF,   g_f);

    dim3 blk(256);
    dim3 gProj(D_MODEL / 128, M_ROWS / 128);   // (8, 64)
    dim3 gFF1 (D_FF   / 128, M_ROWS / 128);    // (32, 64)
    dim3 gFF2 (D_MODEL / 128, M_ROWS / 128);
    dim3 gAttn(SEQ / 64, N_HEADS, BATCH);

    // QKV projections
    sgemm_bias_kernel<<<gProj, blk>>>(x, Wq, bq, pQ, M_ROWS, D_MODEL, D_MODEL, 0);
    sgemm_bias_kernel<<<gProj, blk>>>(x, Wk, bk, pK, M_ROWS, D_MODEL, D_MODEL, 0);
    sgemm_bias_kernel<<<gProj, blk>>>(x, Wv, bv, pV, M_ROWS, D_MODEL, D_MODEL, 0);

    // attention
    attn_kernel<<<gAttn, blk>>>(pQ, pK, pV, pCtx);

    // output projection
    sgemm_bias_kernel<<<gProj, blk>>>(pCtx, Wo, bo, pPrj, M_ROWS, D_MODEL, D_MODEL, 0);

    // residual + LN1
    add_ln_kernel<<<M_ROWS, blk>>>(pPrj, x, ln1_g, ln1_b, pH);

    // FFN
    sgemm_bias_kernel<<<gFF1, blk>>>(pH, W1, b1, pMid, M_ROWS, D_FF, D_MODEL, 1);
    sgemm_bias_kernel<<<gFF2, blk>>>(pMid, W2, b2, pF, M_ROWS, D_MODEL, D_FF, 0);

    // residual + LN2 -> output
    add_ln_kernel<<<M_ROWS, blk>>>(pF, pH, ln2_g, ln2_b, out);
}

// round 6
// speedup vs baseline: 1.4940x; 1.4940x over previous
#include <cuda_runtime.h>
#include <cuda_bf16.h>
#include <cstdint>
#include <stdint.h>
#include <math.h>

// ---------------------------------------------------------------------------
// Transformer encoder block. GEMMs on tensor cores (tf32 mma.sync),
// attention fp32 flash-style, fused add+LN.
// B=4, S=2048, D=1024, H=16, d_k=64, FFN=4096
// ---------------------------------------------------------------------------

#define D_MODEL 1024
#define N_HEADS 16
#define D_K     64
#define D_FF    4096
#define SEQ     2048
#define BATCH   4
#define M_ROWS  (BATCH * SEQ)          // 8192

// Scratch (device globals; allocation in kernel_launch is forbidden)
__device__ float g_Q  [M_ROWS * D_MODEL];
__device__ float g_K  [M_ROWS * D_MODEL];
__device__ float g_V  [M_ROWS * D_MODEL];
__device__ float g_ctx[M_ROWS * D_MODEL];
__device__ float g_prj[M_ROWS * D_MODEL];
__device__ float g_h  [M_ROWS * D_MODEL];
__device__ float g_mid[(size_t)M_ROWS * D_FF];
__device__ float g_f  [M_ROWS * D_MODEL];

// ---------------------------------------------------------------------------
// TF32 tensor-core GEMM: C[M,N] = A[M,K] @ B[K,N] + bias (+ optional ReLU)
// BM=128, BN=128, BK=32, 256 threads (8 warps), warp tile 64x32,
// mma.sync.m16n8k8.tf32, cp.async double-buffered.
// Requires M%128==0, N%128==0, K%32==0.
// ---------------------------------------------------------------------------
#define AS_STRIDE 36    // 32 k + 4 pad  -> A frag loads conflict-free
#define BS_STRIDE 136   // 128 n + 8 pad -> B frag loads conflict-free
#define AS_ELEMS  (128 * AS_STRIDE)   // 4608
#define BS_ELEMS  (32  * BS_STRIDE)   // 4352
#define GEMM_SMEM_BYTES ((2 * AS_ELEMS + 2 * BS_ELEMS) * 4)  // 71680

__device__ __forceinline__ void cp16(uint32_t s, const float* g) {
    asm volatile("cp.async.cg.shared.global [%0], [%1], 16;\n" :: "r"(s), "l"(g));
}
__device__ __forceinline__ void cp_commit() {
    asm volatile("cp.async.commit_group;\n" ::: "memory");
}

__device__ __forceinline__ void mma_tf32(
    float& c0, float& c1, float& c2, float& c3,
    uint32_t a0, uint32_t a1, uint32_t a2, uint32_t a3,
    uint32_t b0, uint32_t b1)
{
    asm volatile(
        "mma.sync.aligned.m16n8k8.row.col.f32.tf32.tf32.f32 "
        "{%0,%1,%2,%3}, {%4,%5,%6,%7}, {%8,%9}, {%0,%1,%2,%3};\n"
        : "+f"(c0), "+f"(c1), "+f"(c2), "+f"(c3)
        : "r"(a0), "r"(a1), "r"(a2), "r"(a3), "r"(b0), "r"(b1));
}

__global__ __launch_bounds__(256) void tf32_gemm_kernel(
    const float* __restrict__ A, const float* __restrict__ B,
    const float* __restrict__ bias, float* __restrict__ C,
    int M, int N, int K, int relu)
{
    extern __shared__ float smem[];
    float* Asb[2] = { smem, smem + AS_ELEMS };
    float* Bsb[2] = { smem + 2 * AS_ELEMS, smem + 2 * AS_ELEMS + BS_ELEMS };

    const int tid  = threadIdx.x;
    const int lane = tid & 31;
    const int warp = tid >> 5;
    const int wm   = (warp >> 2) * 64;     // warp m-offset within block tile
    const int wn   = (warp & 3) * 32;      // warp n-offset
    const int r    = lane >> 2;            // 0..7
    const int c    = lane & 3;             // 0..3
    const int bm   = blockIdx.y;
    const int bn   = blockIdx.x;

    const float* Ab = A + (size_t)bm * 128 * K;
    const float* Bb = B + (size_t)bn * 128;

    uint32_t asAddr[2], bsAddr[2];
    asAddr[0] = (uint32_t)__cvta_generic_to_shared(Asb[0]);
    asAddr[1] = (uint32_t)__cvta_generic_to_shared(Asb[1]);
    bsAddr[0] = (uint32_t)__cvta_generic_to_shared(Bsb[0]);
    bsAddr[1] = (uint32_t)__cvta_generic_to_shared(Bsb[1]);

    float acc[4][4][4];
    #pragma unroll
    for (int i = 0; i < 4; i++)
        #pragma unroll
        for (int j = 0; j < 4; j++)
            #pragma unroll
            for (int k = 0; k < 4; k++) acc[i][j][k] = 0.0f;

    const int KT = K / 32;

    // issue loads for k-tile kk into buffer b
    auto issue = [&](int kk, int b) {
        #pragma unroll
        for (int i = 0; i < 4; i++) {
            int id = tid + i * 256;
            int ar = id >> 3, ac = (id & 7) * 4;           // A: 128 rows x 8 chunks
            cp16(asAddr[b] + (uint32_t)(ar * AS_STRIDE + ac) * 4,
                 Ab + (size_t)ar * K + kk + ac);
            int br = id >> 5, bc = (id & 31) * 4;          // B: 32 rows x 32 chunks
            cp16(bsAddr[b] + (uint32_t)(br * BS_STRIDE + bc) * 4,
                 Bb + (size_t)(kk + br) * N + bc);
        }
        cp_commit();
    };

    issue(0, 0);
    int buf = 0;

    for (int kt = 0; kt < KT; kt++) {
        if (kt + 1 < KT) {
            issue((kt + 1) * 32, buf ^ 1);
            asm volatile("cp.async.wait_group 1;\n" ::: "memory");
        } else {
            asm volatile("cp.async.wait_group 0;\n" ::: "memory");
        }
        __syncthreads();

        const float* As = Asb[buf];
        const float* Bs = Bsb[buf];

        #pragma unroll
        for (int ks = 0; ks < 4; ks++) {
            const int k0 = ks * 8;
            uint32_t af[4][4], bf[4][2];
            #pragma unroll
            for (int ma = 0; ma < 4; ma++) {
                const float* ap = As + (wm + ma * 16 + r) * AS_STRIDE + k0 + c;
                af[ma][0] = __float_as_uint(ap[0]);
                af[ma][2] = __float_as_uint(ap[4]);
                af[ma][1] = __float_as_uint(ap[8 * AS_STRIDE]);
                af[ma][3] = __float_as_uint(ap[8 * AS_STRIDE + 4]);
            }
            #pragma unroll
            for (int na = 0; na < 4; na++) {
                const float* bp = Bs + (k0 + c) * BS_STRIDE + wn + na * 8 + r;
                bf[na][0] = __float_as_uint(bp[0]);
                bf[na][1] = __float_as_uint(bp[4 * BS_STRIDE]);
            }
            #pragma unroll
            for (int ma = 0; ma < 4; ma++)
                #pragma unroll
                for (int na = 0; na < 4; na++)
                    mma_tf32(acc[ma][na][0], acc[ma][na][1],
                             acc[ma][na][2], acc[ma][na][3],
                             af[ma][0], af[ma][1], af[ma][2], af[ma][3],
                             bf[na][0], bf[na][1]);
        }
        __syncthreads();
        buf ^= 1;
    }

    // epilogue: bias (+ relu), float2 stores
    #pragma unroll
    for (int ma = 0; ma < 4; ma++) {
        const int row0 = bm * 128 + wm + ma * 16 + r;
        #pragma unroll
        for (int na = 0; na < 4; na++) {
            const int col = bn * 128 + wn + na * 8 + 2 * c;
            const float bv0 = bias[col];
            const float bv1 = bias[col + 1];
            float v0 = acc[ma][na][0] + bv0;
            float v1 = acc[ma][na][1] + bv1;
            float v2 = acc[ma][na][2] + bv0;
            float v3 = acc[ma][na][3] + bv1;
            if (relu) {
                v0 = fmaxf(v0, 0.f); v1 = fmaxf(v1, 0.f);
                v2 = fmaxf(v2, 0.f); v3 = fmaxf(v3, 0.f);
            }
            float2 p0 = make_float2(v0, v1);
            float2 p1 = make_float2(v2, v3);
            *(float2*)(C + (size_t)row0 * N + col)       = p0;
            *(float2*)(C + (size_t)(row0 + 8) * N + col) = p1;
        }
    }
}

// ---------------------------------------------------------------------------
// Flash-attention style kernel (fp32).
// grid: (SEQ/64, N_HEADS, BATCH), block 256.
// ---------------------------------------------------------------------------
__global__ __launch_bounds__(256) void attn_kernel(
    const float* __restrict__ Q, const float* __restrict__ K,
    const float* __restrict__ V, float* __restrict__ O)
{
    const int b  = blockIdx.z;
    const int h  = blockIdx.y;
    const int qt = blockIdx.x;
    const int tid = threadIdx.x;

    __shared__ float Qs[64][68];
    __shared__ float KVs[32][68];
    __shared__ float Ps[64][33];
    __shared__ float m_s[64], l_s[64], fac_s[64], tmax_s[64], tsum_s[64];

    const size_t qrow0 = (size_t)b * SEQ + (size_t)qt * 64;
    const float* Qb = Q + qrow0 * D_MODEL + h * D_K;
    const float* Kb = K + (size_t)b * SEQ * D_MODEL + h * D_K;
    const float* Vb = V + (size_t)b * SEQ * D_MODEL + h * D_K;

    for (int t = tid; t < 64 * 16; t += 256) {
        int r = t >> 4, c4 = (t & 15) * 4;
        *(float4*)&Qs[r][c4] = *(const float4*)(Qb + (size_t)r * D_MODEL + c4);
    }
    if (tid < 64) { m_s[tid] = -1e30f; l_s[tid] = 0.0f; }

    const int is0 = (tid >> 3) * 2;
    const int js0 = (tid & 7) * 4;
    const int io0 = (tid >> 4) * 4;
    const int d0  = (tid & 15) * 4;

    float o[4][4];
    #pragma unroll
    for (int r = 0; r < 4; r++)
        #pragma unroll
        for (int c = 0; c < 4; c++) o[r][c] = 0.0f;

    __syncthreads();

    for (int kt = 0; kt < SEQ / 32; kt++) {
        for (int t = tid; t < 32 * 16; t += 256) {
            int r = t >> 4, c4 = (t & 15) * 4;
            *(float4*)&KVs[r][c4] =
                *(const float4*)(Kb + (size_t)(kt * 32 + r) * D_MODEL + c4);
        }
        __syncthreads();

        float s[2][4];
        #pragma unroll
        for (int r = 0; r < 2; r++)
            #pragma unroll
            for (int c = 0; c < 4; c++) s[r][c] = 0.0f;

        #pragma unroll
        for (int d = 0; d < 64; d += 4) {
            float4 q0 = *(float4*)&Qs[is0][d];
            float4 q1 = *(float4*)&Qs[is0 + 1][d];
            #pragma unroll
            for (int c = 0; c < 4; c++) {
                float4 kv = *(float4*)&KVs[js0 + c][d];
                s[0][c] += q0.x * kv.x + q0.y * kv.y + q0.z * kv.z + q0.w * kv.w;
                s[1][c] += q1.x * kv.x + q1.y * kv.y + q1.z * kv.z + q1.w * kv.w;
            }
        }
        #pragma unroll
        for (int r = 0; r < 2; r++)
            #pragma unroll
            for (int c = 0; c < 4; c++) s[r][c] *= 0.125f;

        #pragma unroll
        for (int r = 0; r < 2; r++) {
            float mx = fmaxf(fmaxf(s[r][0], s[r][1]), fmaxf(s[r][2], s[r][3]));
            mx = fmaxf(mx, __shfl_xor_sync(0xffffffffu, mx, 1));
            mx = fmaxf(mx, __shfl_xor_sync(0xffffffffu, mx, 2));
            mx = fmaxf(mx, __shfl_xor_sync(0xffffffffu, mx, 4));
            if ((tid & 7) == 0) tmax_s[is0 + r] = mx;
        }
        __syncthreads();

        if (tid < 64) {
            float mo = m_s[tid];
            float mn = fmaxf(mo, tmax_s[tid]);
            fac_s[tid] = __expf(mo - mn);
            m_s[tid] = mn;
        }
        __syncthreads();

        #pragma unroll
        for (int r = 0; r < 2; r++) {
            float mn = m_s[is0 + r];
            float sum = 0.0f;
            #pragma unroll
            for (int c = 0; c < 4; c++) {
                float p = __expf(s[r][c] - mn);
                Ps[is0 + r][js0 + c] = p;
                sum += p;
            }
            sum += __shfl_xor_sync(0xffffffffu, sum, 1);
            sum += __shfl_xor_sync(0xffffffffu, sum, 2);
            sum += __shfl_xor_sync(0xffffffffu, sum, 4);
            if ((tid & 7) == 0) tsum_s[is0 + r] = sum;
        }
        __syncthreads();

        if (tid < 64) l_s[tid] = l_s[tid] * fac_s[tid] + tsum_s[tid];

        for (int t = tid; t < 32 * 16; t += 256) {
            int r = t >> 4, c4 = (t & 15) * 4;
            *(float4*)&KVs[r][c4] =
                *(const float4*)(Vb + (size_t)(kt * 32 + r) * D_MODEL + c4);
        }
        __syncthreads();

        float f0 = fac_s[io0 + 0], f1 = fac_s[io0 + 1];
        float f2 = fac_s[io0 + 2], f3 = fac_s[io0 + 3];
        #pragma unroll
        for (int c = 0; c < 4; c++) {
            o[0][c] *= f0; o[1][c] *= f1; o[2][c] *= f2; o[3][c] *= f3;
        }
        #pragma unroll
        for (int j = 0; j < 32; j++) {
            float4 v4 = *(float4*)&KVs[j][d0];
            float p0 = Ps[io0 + 0][j];
            float p1 = Ps[io0 + 1][j];
            float p2 = Ps[io0 + 2][j];
            float p3 = Ps[io0 + 3][j];
            o[0][0] += p0 * v4.x; o[0][1] += p0 * v4.y; o[0][2] += p0 * v4.z; o[0][3] += p0 * v4.w;
            o[1][0] += p1 * v4.x; o[1][1] += p1 * v4.y; o[1][2] += p1 * v4.z; o[1][3] += p1 * v4.w;
            o[2][0] += p2 * v4.x; o[2][1] += p2 * v4.y; o[2][2] += p2 * v4.z; o[2][3] += p2 * v4.w;
            o[3][0] += p3 * v4.x; o[3][1] += p3 * v4.y; o[3][2] += p3 * v4.z; o[3][3] += p3 * v4.w;
        }
        __syncthreads();
    }

    #pragma unroll
    for (int r = 0; r < 4; r++) {
        float inv = 1.0f / l_s[io0 + r];
        float4 res;
        res.x = o[r][0] * inv; res.y = o[r][1] * inv;
        res.z = o[r][2] * inv; res.w = o[r][3] * inv;
        *(float4*)(O + (qrow0 + io0 + r) * D_MODEL + h * D_K + d0) = res;
    }
}

// ---------------------------------------------------------------------------
// Fused residual-add + LayerNorm: out = LN(a + b) * g + beta
// ---------------------------------------------------------------------------
__global__ __launch_bounds__(256) void add_ln_kernel(
    const float* __restrict__ a, const float* __restrict__ b,
    const float* __restrict__ g, const float* __restrict__ beta,
    float* __restrict__ out)
{
    const int row = blockIdx.x;
    const int tid = threadIdx.x;

    const float4 av = *(const float4*)(a + (size_t)row * D_MODEL + tid * 4);
    const float4 bv = *(const float4*)(b + (size_t)row * D_MODEL + tid * 4);
    float4 v;
    v.x = av.x + bv.x; v.y = av.y + bv.y; v.z = av.z + bv.z; v.w = av.w + bv.w;

    float s  = v.x + v.y + v.z + v.w;
    float sq = v.x * v.x + v.y * v.y + v.z * v.z + v.w * v.w;

    #pragma unroll
    for (int off = 16; off; off >>= 1) {
        s  += __shfl_xor_sync(0xffffffffu, s,  off);
        sq += __shfl_xor_sync(0xffffffffu, sq, off);
    }
    __shared__ float red_s[8], red_q[8];
    if ((tid & 31) == 0) { red_s[tid >> 5] = s; red_q[tid >> 5] = sq; }
    __syncthreads();
    __shared__ float smean, srstd;
    if (tid == 0) {
        float ts = 0.f, tq = 0.f;
        #pragma unroll
        for (int i = 0; i < 8; i++) { ts += red_s[i]; tq += red_q[i]; }
        float mean = ts * (1.0f / D_MODEL);
        float var  = tq * (1.0f / D_MODEL) - mean * mean;
        smean = mean;
        srstd = rsqrtf(var + 1e-5f);
    }
    __syncthreads();
    const float mean = smean, rstd = srstd;

    const float4 gv = *(const float4*)(g    + tid * 4);
    const float4 tv = *(const float4*)(beta + tid * 4);
    float4 o;
    o.x = (v.x - mean) * rstd * gv.x + tv.x;
    o.y = (v.y - mean) * rstd * gv.y + tv.y;
    o.z = (v.z - mean) * rstd * gv.z + tv.z;
    o.w = (v.w - mean) * rstd * gv.w + tv.w;
    *(float4*)(out + (size_t)row * D_MODEL + tid * 4) = o;
}

// ---------------------------------------------------------------------------
// Launch
// ---------------------------------------------------------------------------
extern "C" void kernel_launch(void* const* d_in, const int* in_sizes, int n_in,
                              void* d_out, int out_size)
{
    const float* x     = (const float*)d_in[0];
    const float* Wq    = (const float*)d_in[1];
    const float* bq    = (const float*)d_in[2];
    const float* Wk    = (const float*)d_in[3];
    const float* bk    = (const float*)d_in[4];
    const float* Wv    = (const float*)d_in[5];
    const float* bv    = (const float*)d_in[6];
    const float* Wo    = (const float*)d_in[7];
    const float* bo    = (const float*)d_in[8];
    const float* ln1_g = (const float*)d_in[9];
    const float* ln1_b = (const float*)d_in[10];
    const float* W1    = (const float*)d_in[11];
    const float* b1    = (const float*)d_in[12];
    const float* W2    = (const float*)d_in[13];
    const float* b2    = (const float*)d_in[14];
    const float* ln2_g = (const float*)d_in[15];
    const float* ln2_b = (const float*)d_in[16];
    float* out = (float*)d_out;

    float *pQ, *pK, *pV, *pCtx, *pPrj, *pH, *pMid, *pF;
    cudaGetSymbolAddress((void**)&pQ,   g_Q);
    cudaGetSymbolAddress((void**)&pK,   g_K);
    cudaGetSymbolAddress((void**)&pV,   g_V);
    cudaGetSymbolAddress((void**)&pCtx, g_ctx);
    cudaGetSymbolAddress((void**)&pPrj, g_prj);
    cudaGetSymbolAddress((void**)&pH,   g_h);
    cudaGetSymbolAddress((void**)&pMid, g_mid);
    cudaGetSymbolAddress((void**)&pF,   g_f);

    cudaFuncSetAttribute(tf32_gemm_kernel,
                         cudaFuncAttributeMaxDynamicSharedMemorySize,
                         GEMM_SMEM_BYTES);

    dim3 blk(256);
    dim3 gProj(D_MODEL / 128, M_ROWS / 128);   // (8, 64)
    dim3 gFF1 (D_FF   / 128, M_ROWS / 128);    // (32, 64)
    dim3 gFF2 (D_MODEL / 128, M_ROWS / 128);
    dim3 gAttn(SEQ / 64, N_HEADS, BATCH);

    // QKV projections
    tf32_gemm_kernel<<<gProj, blk, GEMM_SMEM_BYTES>>>(x, Wq, bq, pQ, M_ROWS, D_MODEL, D_MODEL, 0);
    tf32_gemm_kernel<<<gProj, blk, GEMM_SMEM_BYTES>>>(x, Wk, bk, pK, M_ROWS, D_MODEL, D_MODEL, 0);
    tf32_gemm_kernel<<<gProj, blk, GEMM_SMEM_BYTES>>>(x, Wv, bv, pV, M_ROWS, D_MODEL, D_MODEL, 0);

    // attention
    attn_kernel<<<gAttn, blk>>>(pQ, pK, pV, pCtx);

    // output projection
    tf32_gemm_kernel<<<gProj, blk, GEMM_SMEM_BYTES>>>(pCtx, Wo, bo, pPrj, M_ROWS, D_MODEL, D_MODEL, 0);

    // residual + LN1
    add_ln_kernel<<<M_ROWS, blk>>>(pPrj, x, ln1_g, ln1_b, pH);

    // FFN
    tf32_gemm_kernel<<<gFF1, blk, GEMM_SMEM_BYTES>>>(pH, W1, b1, pMid, M_ROWS, D_FF, D_MODEL, 1);
    tf32_gemm_kernel<<<gFF2, blk, GEMM_SMEM_BYTES>>>(pMid, W2, b2, pF, M_ROWS, D_MODEL, D_FF, 0);

    // residual + LN2 -> output
    add_ln_kernel<<<M_ROWS, blk>>>(pF, pH, ln2_g, ln2_b, out);
}

// round 7
// speedup vs baseline: 4.3154x; 2.8885x over previous
#include <cuda_runtime.h>
#include <cuda_bf16.h>
#include <cstdint>
#include <stdint.h>
#include <math.h>

// ---------------------------------------------------------------------------
// Transformer encoder block. All matmul work (GEMMs + attention) on tensor
// cores via tf32 mma.sync. B=4, S=2048, D=1024, H=16, d_k=64, FFN=4096
// ---------------------------------------------------------------------------

#define D_MODEL 1024
#define N_HEADS 16
#define D_K     64
#define D_FF    4096
#define SEQ     2048
#define BATCH   4
#define M_ROWS  (BATCH * SEQ)          // 8192

// Scratch (device globals; allocation in kernel_launch is forbidden)
__device__ float g_Q  [M_ROWS * D_MODEL];
__device__ float g_K  [M_ROWS * D_MODEL];
__device__ float g_V  [M_ROWS * D_MODEL];
__device__ float g_ctx[M_ROWS * D_MODEL];
__device__ float g_prj[M_ROWS * D_MODEL];
__device__ float g_h  [M_ROWS * D_MODEL];
__device__ float g_mid[(size_t)M_ROWS * D_FF];
__device__ float g_f  [M_ROWS * D_MODEL];

__device__ __forceinline__ void cp16(uint32_t s, const float* g) {
    asm volatile("cp.async.cg.shared.global [%0], [%1], 16;\n" :: "r"(s), "l"(g));
}
__device__ __forceinline__ void cp_commit() {
    asm volatile("cp.async.commit_group;\n" ::: "memory");
}

__device__ __forceinline__ void mma_tf32(
    float& c0, float& c1, float& c2, float& c3,
    uint32_t a0, uint32_t a1, uint32_t a2, uint32_t a3,
    uint32_t b0, uint32_t b1)
{
    asm volatile(
        "mma.sync.aligned.m16n8k8.row.col.f32.tf32.tf32.f32 "
        "{%0,%1,%2,%3}, {%4,%5,%6,%7}, {%8,%9}, {%0,%1,%2,%3};\n"
        : "+f"(c0), "+f"(c1), "+f"(c2), "+f"(c3)
        : "r"(a0), "r"(a1), "r"(a2), "r"(a3), "r"(b0), "r"(b1));
}

// ---------------------------------------------------------------------------
// TF32 tensor-core GEMM: C[M,N] = A[M,K] @ B[K,N] + bias (+ optional ReLU)
// BM=128, BN=128, BK=32, 256 threads (8 warps), warp tile 64x32.
// ---------------------------------------------------------------------------
#define AS_STRIDE 36
#define BS_STRIDE 136
#define AS_ELEMS  (128 * AS_STRIDE)
#define BS_ELEMS  (32  * BS_STRIDE)
#define GEMM_SMEM_BYTES ((2 * AS_ELEMS + 2 * BS_ELEMS) * 4)  // 71680

__global__ __launch_bounds__(256) void tf32_gemm_kernel(
    const float* __restrict__ A, const float* __restrict__ B,
    const float* __restrict__ bias, float* __restrict__ C,
    int M, int N, int K, int relu)
{
    extern __shared__ float smem[];
    float* Asb[2] = { smem, smem + AS_ELEMS };
    float* Bsb[2] = { smem + 2 * AS_ELEMS, smem + 2 * AS_ELEMS + BS_ELEMS };

    const int tid  = threadIdx.x;
    const int lane = tid & 31;
    const int warp = tid >> 5;
    const int wm   = (warp >> 2) * 64;
    const int wn   = (warp & 3) * 32;
    const int r    = lane >> 2;
    const int c    = lane & 3;
    const int bm   = blockIdx.y;
    const int bn   = blockIdx.x;

    const float* Ab = A + (size_t)bm * 128 * K;
    const float* Bb = B + (size_t)bn * 128;

    uint32_t asAddr[2], bsAddr[2];
    asAddr[0] = (uint32_t)__cvta_generic_to_shared(Asb[0]);
    asAddr[1] = (uint32_t)__cvta_generic_to_shared(Asb[1]);
    bsAddr[0] = (uint32_t)__cvta_generic_to_shared(Bsb[0]);
    bsAddr[1] = (uint32_t)__cvta_generic_to_shared(Bsb[1]);

    float acc[4][4][4];
    #pragma unroll
    for (int i = 0; i < 4; i++)
        #pragma unroll
        for (int j = 0; j < 4; j++)
            #pragma unroll
            for (int k = 0; k < 4; k++) acc[i][j][k] = 0.0f;

    const int KT = K / 32;

    auto issue = [&](int kk, int b) {
        #pragma unroll
        for (int i = 0; i < 4; i++) {
            int id = tid + i * 256;
            int ar = id >> 3, ac = (id & 7) * 4;
            cp16(asAddr[b] + (uint32_t)(ar * AS_STRIDE + ac) * 4,
                 Ab + (size_t)ar * K + kk + ac);
            int br = id >> 5, bc = (id & 31) * 4;
            cp16(bsAddr[b] + (uint32_t)(br * BS_STRIDE + bc) * 4,
                 Bb + (size_t)(kk + br) * N + bc);
        }
        cp_commit();
    };

    issue(0, 0);
    int buf = 0;

    for (int kt = 0; kt < KT; kt++) {
        if (kt + 1 < KT) {
            issue((kt + 1) * 32, buf ^ 1);
            asm volatile("cp.async.wait_group 1;\n" ::: "memory");
        } else {
            asm volatile("cp.async.wait_group 0;\n" ::: "memory");
        }
        __syncthreads();

        const float* As = Asb[buf];
        const float* Bs = Bsb[buf];

        #pragma unroll
        for (int ks = 0; ks < 4; ks++) {
            const int k0 = ks * 8;
            uint32_t af[4][4], bf[4][2];
            #pragma unroll
            for (int ma = 0; ma < 4; ma++) {
                const float* ap = As + (wm + ma * 16 + r) * AS_STRIDE + k0 + c;
                af[ma][0] = __float_as_uint(ap[0]);
                af[ma][2] = __float_as_uint(ap[4]);
                af[ma][1] = __float_as_uint(ap[8 * AS_STRIDE]);
                af[ma][3] = __float_as_uint(ap[8 * AS_STRIDE + 4]);
            }
            #pragma unroll
            for (int na = 0; na < 4; na++) {
                const float* bp = Bs + (k0 + c) * BS_STRIDE + wn + na * 8 + r;
                bf[na][0] = __float_as_uint(bp[0]);
                bf[na][1] = __float_as_uint(bp[4 * BS_STRIDE]);
            }
            #pragma unroll
            for (int ma = 0; ma < 4; ma++)
                #pragma unroll
                for (int na = 0; na < 4; na++)
                    mma_tf32(acc[ma][na][0], acc[ma][na][1],
                             acc[ma][na][2], acc[ma][na][3],
                             af[ma][0], af[ma][1], af[ma][2], af[ma][3],
                             bf[na][0], bf[na][1]);
        }
        __syncthreads();
        buf ^= 1;
    }

    #pragma unroll
    for (int ma = 0; ma < 4; ma++) {
        const int row0 = bm * 128 + wm + ma * 16 + r;
        #pragma unroll
        for (int na = 0; na < 4; na++) {
            const int col = bn * 128 + wn + na * 8 + 2 * c;
            const float bv0 = bias[col];
            const float bv1 = bias[col + 1];
            float v0 = acc[ma][na][0] + bv0;
            float v1 = acc[ma][na][1] + bv1;
            float v2 = acc[ma][na][2] + bv0;
            float v3 = acc[ma][na][3] + bv1;
            if (relu) {
                v0 = fmaxf(v0, 0.f); v1 = fmaxf(v1, 0.f);
                v2 = fmaxf(v2, 0.f); v3 = fmaxf(v3, 0.f);
            }
            float2 p0 = make_float2(v0, v1);
            float2 p1 = make_float2(v2, v3);
            *(float2*)(C + (size_t)row0 * N + col)       = p0;
            *(float2*)(C + (size_t)(row0 + 8) * N + col) = p1;
        }
    }
}

// ---------------------------------------------------------------------------
// Flash attention on tensor cores (tf32 mma).
// Block: 128 q-rows, 256 threads (8 warps x 16 rows). K/V tile: 64 keys.
// grid: (SEQ/128, N_HEADS, BATCH) = (16, 16, 4)
// Q fragments live in registers for the whole kernel (pre-scaled by 1/8).
// Smem strides chosen so every fragment LDS is bank-conflict-free:
//   Ks stride 68: bank = 4r + c   (bijective over warp)
//   Ps stride 68: bank = 4r + c
//   Vs stride 72: bank = 8c + r
// ---------------------------------------------------------------------------
#define ATT_QT   128
#define ATT_KT   64
#define KS_STR   68
#define VS_STR   72
#define PS_STR   68
#define KS_ELEMS (ATT_KT * KS_STR)     // 4352
#define VS_ELEMS (ATT_KT * VS_STR)     // 4608
#define PS_ELEMS (ATT_QT * PS_STR)     // 8704
#define ATT_SMEM_BYTES ((KS_ELEMS + VS_ELEMS + PS_ELEMS) * 4)  // 70656

__global__ __launch_bounds__(256) void attn_mma_kernel(
    const float* __restrict__ Q, const float* __restrict__ K,
    const float* __restrict__ V, float* __restrict__ O)
{
    extern __shared__ float sm[];
    float* Ks = sm;
    float* Vs = sm + KS_ELEMS;
    float* Ps = sm + KS_ELEMS + VS_ELEMS;

    const int b    = blockIdx.z;
    const int h    = blockIdx.y;
    const int qt   = blockIdx.x;
    const int tid  = threadIdx.x;
    const int lane = tid & 31;
    const int warp = tid >> 5;
    const int r    = lane >> 2;       // 0..7
    const int c    = lane & 3;        // 0..3
    const int wm   = warp * 16;       // warp's q-row stripe within block

    const size_t qrow0 = (size_t)b * SEQ + (size_t)qt * ATT_QT;
    const float* Qb = Q + qrow0 * D_MODEL + h * D_K;
    const float* Kb = K + (size_t)b * SEQ * D_MODEL + h * D_K;
    const float* Vb = V + (size_t)b * SEQ * D_MODEL + h * D_K;

    // ---- stage Q tile (128x64) into Ps, then load Q fragments to registers
    for (int t = tid; t < ATT_QT * 16; t += 256) {
        int row = t >> 4, c4 = (t & 15) * 4;
        *(float4*)&Ps[row * PS_STR + c4] =
            *(const float4*)(Qb + (size_t)row * D_MODEL + c4);
    }
    __syncthreads();

    float qf[8][4];
    #pragma unroll
    for (int kk = 0; kk < 8; kk++) {
        const float* q0 = Ps + (wm + r) * PS_STR + kk * 8 + c;
        const float* q1 = Ps + (wm + r + 8) * PS_STR + kk * 8 + c;
        qf[kk][0] = q0[0] * 0.125f;
        qf[kk][1] = q1[0] * 0.125f;
        qf[kk][2] = q0[4] * 0.125f;
        qf[kk][3] = q1[4] * 0.125f;
    }
    __syncthreads();   // Ps about to be reused for P

    float oacc[8][4];
    #pragma unroll
    for (int nt = 0; nt < 8; nt++)
        #pragma unroll
        for (int i = 0; i < 4; i++) oacc[nt][i] = 0.0f;

    float m0 = -1e30f, m1 = -1e30f, l0 = 0.0f, l1 = 0.0f;

    for (int kt = 0; kt < SEQ / ATT_KT; kt++) {
        // ---- load K and V tiles (64 x 64 each)
        for (int t = tid; t < ATT_KT * 16; t += 256) {
            int row = t >> 4, c4 = (t & 15) * 4;
            const size_t gro = (size_t)(kt * ATT_KT + row) * D_MODEL + c4;
            *(float4*)&Ks[row * KS_STR + c4] = *(const float4*)(Kb + gro);
            *(float4*)&Vs[row * VS_STR + c4] = *(const float4*)(Vb + gro);
        }
        __syncthreads();

        // ---- S = (Q/8) @ K^T : 8 n-tiles (keys), 8 k-steps (dims)
        float sacc[8][4];
        #pragma unroll
        for (int nt = 0; nt < 8; nt++) {
            sacc[nt][0] = sacc[nt][1] = sacc[nt][2] = sacc[nt][3] = 0.0f;
            #pragma unroll
            for (int kk = 0; kk < 8; kk++) {
                const float* kp = Ks + (nt * 8 + r) * KS_STR + kk * 8 + c;
                uint32_t b0 = __float_as_uint(kp[0]);
                uint32_t b1 = __float_as_uint(kp[4]);
                mma_tf32(sacc[nt][0], sacc[nt][1], sacc[nt][2], sacc[nt][3],
                         __float_as_uint(qf[kk][0]), __float_as_uint(qf[kk][1]),
                         __float_as_uint(qf[kk][2]), __float_as_uint(qf[kk][3]),
                         b0, b1);
            }
        }

        // ---- online softmax (thread owns rows wm+r and wm+r+8)
        float tm0 = -1e30f, tm1 = -1e30f;
        #pragma unroll
        for (int nt = 0; nt < 8; nt++) {
            tm0 = fmaxf(tm0, fmaxf(sacc[nt][0], sacc[nt][1]));
            tm1 = fmaxf(tm1, fmaxf(sacc[nt][2], sacc[nt][3]));
        }
        tm0 = fmaxf(tm0, __shfl_xor_sync(0xffffffffu, tm0, 1));
        tm0 = fmaxf(tm0, __shfl_xor_sync(0xffffffffu, tm0, 2));
        tm1 = fmaxf(tm1, __shfl_xor_sync(0xffffffffu, tm1, 1));
        tm1 = fmaxf(tm1, __shfl_xor_sync(0xffffffffu, tm1, 2));

        const float mn0 = fmaxf(m0, tm0);
        const float mn1 = fmaxf(m1, tm1);
        const float fac0 = __expf(m0 - mn0);
        const float fac1 = __expf(m1 - mn1);
        m0 = mn0; m1 = mn1;

        float ts0 = 0.0f, ts1 = 0.0f;
        #pragma unroll
        for (int nt = 0; nt < 8; nt++) {
            float p0 = __expf(sacc[nt][0] - mn0);
            float p1 = __expf(sacc[nt][1] - mn0);
            float p2 = __expf(sacc[nt][2] - mn1);
            float p3 = __expf(sacc[nt][3] - mn1);
            ts0 += p0 + p1;
            ts1 += p2 + p3;
            const int col = nt * 8 + c * 2;
            Ps[(wm + r) * PS_STR + col]     = p0;
            Ps[(wm + r) * PS_STR + col + 1] = p1;
            Ps[(wm + r + 8) * PS_STR + col]     = p2;
            Ps[(wm + r + 8) * PS_STR + col + 1] = p3;
        }
        ts0 += __shfl_xor_sync(0xffffffffu, ts0, 1);
        ts0 += __shfl_xor_sync(0xffffffffu, ts0, 2);
        ts1 += __shfl_xor_sync(0xffffffffu, ts1, 1);
        ts1 += __shfl_xor_sync(0xffffffffu, ts1, 2);
        l0 = l0 * fac0 + ts0;
        l1 = l1 * fac1 + ts1;

        // rescale O accumulators
        #pragma unroll
        for (int nt = 0; nt < 8; nt++) {
            oacc[nt][0] *= fac0; oacc[nt][1] *= fac0;
            oacc[nt][2] *= fac1; oacc[nt][3] *= fac1;
        }

        // P written only to this warp's own rows; same-warp visibility
        __syncwarp();

        // ---- O += P @ V : contraction over 64 keys (8 k-steps), 8 d-tiles
        #pragma unroll
        for (int kk = 0; kk < 8; kk++) {
            const float* pp0 = Ps + (wm + r) * PS_STR + kk * 8 + c;
            const float* pp1 = Ps + (wm + r + 8) * PS_STR + kk * 8 + c;
            uint32_t a0 = __float_as_uint(pp0[0]);
            uint32_t a1 = __float_as_uint(pp1[0]);
            uint32_t a2 = __float_as_uint(pp0[4]);
            uint32_t a3 = __float_as_uint(pp1[4]);
            #pragma unroll
            for (int nt = 0; nt < 8; nt++) {
                const float* vp = Vs + (kk * 8 + c) * VS_STR + nt * 8 + r;
                uint32_t b0 = __float_as_uint(vp[0]);
                uint32_t b1 = __float_as_uint(vp[4 * VS_STR]);
                mma_tf32(oacc[nt][0], oacc[nt][1], oacc[nt][2], oacc[nt][3],
                         a0, a1, a2, a3, b0, b1);
            }
        }
        __syncthreads();   // protect Ks/Vs/Ps before next tile
    }

    // ---- normalize and store
    const float inv0 = 1.0f / l0;
    const float inv1 = 1.0f / l1;
    float* Ob = O + qrow0 * D_MODEL + h * D_K;
    #pragma unroll
    for (int nt = 0; nt < 8; nt++) {
        const int col = nt * 8 + c * 2;
        float2 r0 = make_float2(oacc[nt][0] * inv0, oacc[nt][1] * inv0);
        float2 r1 = make_float2(oacc[nt][2] * inv1, oacc[nt][3] * inv1);
        *(float2*)(Ob + (size_t)(wm + r) * D_MODEL + col)     = r0;
        *(float2*)(Ob + (size_t)(wm + r + 8) * D_MODEL + col) = r1;
    }
}

// ---------------------------------------------------------------------------
// Fused residual-add + LayerNorm: out = LN(a + b) * g + beta
// ---------------------------------------------------------------------------
__global__ __launch_bounds__(256) void add_ln_kernel(
    const float* __restrict__ a, const float* __restrict__ b,
    const float* __restrict__ g, const float* __restrict__ beta,
    float* __restrict__ out)
{
    const int row = blockIdx.x;
    const int tid = threadIdx.x;

    const float4 av = *(const float4*)(a + (size_t)row * D_MODEL + tid * 4);
    const float4 bv = *(const float4*)(b + (size_t)row * D_MODEL + tid * 4);
    float4 v;
    v.x = av.x + bv.x; v.y = av.y + bv.y; v.z = av.z + bv.z; v.w = av.w + bv.w;

    float s  = v.x + v.y + v.z + v.w;
    float sq = v.x * v.x + v.y * v.y + v.z * v.z + v.w * v.w;

    #pragma unroll
    for (int off = 16; off; off >>= 1) {
        s  += __shfl_xor_sync(0xffffffffu, s,  off);
        sq += __shfl_xor_sync(0xffffffffu, sq, off);
    }
    __shared__ float red_s[8], red_q[8];
    if ((tid & 31) == 0) { red_s[tid >> 5] = s; red_q[tid >> 5] = sq; }
    __syncthreads();
    __shared__ float smean, srstd;
    if (tid == 0) {
        float ts = 0.f, tq = 0.f;
        #pragma unroll
        for (int i = 0; i < 8; i++) { ts += red_s[i]; tq += red_q[i]; }
        float mean = ts * (1.0f / D_MODEL);
        float var  = tq * (1.0f / D_MODEL) - mean * mean;
        smean = mean;
        srstd = rsqrtf(var + 1e-5f);
    }
    __syncthreads();
    const float mean = smean, rstd = srstd;

    const float4 gv = *(const float4*)(g    + tid * 4);
    const float4 tv = *(const float4*)(beta + tid * 4);
    float4 o;
    o.x = (v.x - mean) * rstd * gv.x + tv.x;
    o.y = (v.y - mean) * rstd * gv.y + tv.y;
    o.z = (v.z - mean) * rstd * gv.z + tv.z;
    o.w = (v.w - mean) * rstd * gv.w + tv.w;
    *(float4*)(out + (size_t)row * D_MODEL + tid * 4) = o;
}

// ---------------------------------------------------------------------------
// Launch
// ---------------------------------------------------------------------------
extern "C" void kernel_launch(void* const* d_in, const int* in_sizes, int n_in,
                              void* d_out, int out_size)
{
    const float* x     = (const float*)d_in[0];
    const float* Wq    = (const float*)d_in[1];
    const float* bq    = (const float*)d_in[2];
    const float* Wk    = (const float*)d_in[3];
    const float* bk    = (const float*)d_in[4];
    const float* Wv    = (const float*)d_in[5];
    const float* bv    = (const float*)d_in[6];
    const float* Wo    = (const float*)d_in[7];
    const float* bo    = (const float*)d_in[8];
    const float* ln1_g = (const float*)d_in[9];
    const float* ln1_b = (const float*)d_in[10];
    const float* W1    = (const float*)d_in[11];
    const float* b1    = (const float*)d_in[12];
    const float* W2    = (const float*)d_in[13];
    const float* b2    = (const float*)d_in[14];
    const float* ln2_g = (const float*)d_in[15];
    const float* ln2_b = (const float*)d_in[16];
    float* out = (float*)d_out;

    float *pQ, *pK, *pV, *pCtx, *pPrj, *pH, *pMid, *pF;
    cudaGetSymbolAddress((void**)&pQ,   g_Q);
    cudaGetSymbolAddress((void**)&pK,   g_K);
    cudaGetSymbolAddress((void**)&pV,   g_V);
    cudaGetSymbolAddress((void**)&pCtx, g_ctx);
    cudaGetSymbolAddress((void**)&pPrj, g_prj);
    cudaGetSymbolAddress((void**)&pH,   g_h);
    cudaGetSymbolAddress((void**)&pMid, g_mid);
    cudaGetSymbolAddress((void**)&pF,   g_f);

    cudaFuncSetAttribute(tf32_gemm_kernel,
                         cudaFuncAttributeMaxDynamicSharedMemorySize,
                         GEMM_SMEM_BYTES);
    cudaFuncSetAttribute(attn_mma_kernel,
                         cudaFuncAttributeMaxDynamicSharedMemorySize,
                         ATT_SMEM_BYTES);

    dim3 blk(256);
    dim3 gProj(D_MODEL / 128, M_ROWS / 128);   // (8, 64)
    dim3 gFF1 (D_FF   / 128, M_ROWS / 128);    // (32, 64)
    dim3 gFF2 (D_MODEL / 128, M_ROWS / 128);
    dim3 gAttn(SEQ / ATT_QT, N_HEADS, BATCH);  // (16, 16, 4)

    // QKV projections
    tf32_gemm_kernel<<<gProj, blk, GEMM_SMEM_BYTES>>>(x, Wq, bq, pQ, M_ROWS, D_MODEL, D_MODEL, 0);
    tf32_gemm_kernel<<<gProj, blk, GEMM_SMEM_BYTES>>>(x, Wk, bk, pK, M_ROWS, D_MODEL, D_MODEL, 0);
    tf32_gemm_kernel<<<gProj, blk, GEMM_SMEM_BYTES>>>(x, Wv, bv, pV, M_ROWS, D_MODEL, D_MODEL, 0);

    // attention (tensor-core)
    attn_mma_kernel<<<gAttn, blk, ATT_SMEM_BYTES>>>(pQ, pK, pV, pCtx);

    // output projection
    tf32_gemm_kernel<<<gProj, blk, GEMM_SMEM_BYTES>>>(pCtx, Wo, bo, pPrj, M_ROWS, D_MODEL, D_MODEL, 0);

    // residual + LN1
    add_ln_kernel<<<M_ROWS, blk>>>(pPrj, x, ln1_g, ln1_b, pH);

    // FFN
    tf32_gemm_kernel<<<gFF1, blk, GEMM_SMEM_BYTES>>>(pH, W1, b1, pMid, M_ROWS, D_FF, D_MODEL, 1);
    tf32_gemm_kernel<<<gFF2, blk, GEMM_SMEM_BYTES>>>(pMid, W2, b2, pF, M_ROWS, D_MODEL, D_FF, 0);

    // residual + LN2 -> output
    add_ln_kernel<<<M_ROWS, blk>>>(pF, pH, ln2_g, ln2_b, out);
}